// round 11
// baseline (speedup 1.0000x reference)
#include <cuda_runtime.h>
#include <cstdint>

// NetVLAD fused pool, 3-product BF16 mma.sync m16n8k16, sm_103a. Round 11.
// R read from global EXACTLY ONCE (stage-A fragment loads); Rn (n-pair packed)
// built from those registers via shfl_xor(4) partner exchange. 3 CTA/SM.

#define MMA_BF16(d0,d1,d2,d3, a0,a1,a2,a3, b0,b1) \
  asm volatile("mma.sync.aligned.m16n8k16.row.col.f32.bf16.bf16.f32 " \
      "{%0,%1,%2,%3},{%4,%5,%6,%7},{%8,%9},{%0,%1,%2,%3};" \
      : "+f"(d0),"+f"(d1),"+f"(d2),"+f"(d3) \
      : "r"(a0),"r"(a1),"r"(a2),"r"(a3),"r"(b0),"r"(b1))
#define CVT2(d, lo, hi) \
  asm("cvt.rn.satfinite.bf16x2.f32 %0, %1, %2;" : "=r"(d) : "f"(hi), "f"(lo))

__device__ __forceinline__ float lo16f(uint32_t x){ return __uint_as_float(x << 16); }
__device__ __forceinline__ float hi16f(uint32_t x){ return __uint_as_float(x & 0xFFFF0000u); }
__device__ __forceinline__ void pair2(float x, float y, uint32_t& H, uint32_t& L){
    CVT2(H, x, y);
    CVT2(L, x - lo16f(H), y - hi16f(H));
}
#define SHF4(v) __shfl_xor_sync(~0u, v, 4)

namespace {
constexpr int Nn = 2048, Cc = 64, Kk = 32;
constexpr int SPLIT = 8, NT = 128;
constexpr int TILES = (Nn / SPLIT) / NT;   // 2
constexpr int RNP = 72, WCP = 36, AKP = 68;
constexpr int O_RNH = 0;
constexpr int O_RNL = O_RNH + 64 * RNP;
constexpr int O_WCH = O_RNL + 64 * RNP;
constexpr int O_WCL = O_WCH + Kk * WCP;
constexpr int O_AKH = O_WCL + Kk * WCP;
constexpr int O_AKL = O_AKH + Kk * AKP;
constexpr int O_AS  = O_AKL + Kk * AKP;
constexpr int O_BS  = O_AS + 32;
constexpr int SMEM_BYTES = (O_BS + 32) * 4;   // 63,744 B -> 3 CTAs/SM
}

__global__ void nv_zero(float4* __restrict__ out, int n4) {
    int i = blockIdx.x * blockDim.x + threadIdx.x;
    if (i < n4) out[i] = make_float4(0.f, 0.f, 0.f, 0.f);
}

__global__ __launch_bounds__(256, 3) void nv_tc(
    const float* __restrict__ R, const float* __restrict__ W,
    const float* __restrict__ bvec, const float* __restrict__ cent,
    float* __restrict__ out)
{
    extern __shared__ float sm[];
    uint32_t* RNH = (uint32_t*)(sm + O_RNH);
    uint32_t* RNL = (uint32_t*)(sm + O_RNL);
    uint32_t* WCH = (uint32_t*)(sm + O_WCH);
    uint32_t* WCL = (uint32_t*)(sm + O_WCL);
    uint32_t* AKH = (uint32_t*)(sm + O_AKH);
    uint32_t* AKL = (uint32_t*)(sm + O_AKL);
    float* asum_sm = sm + O_AS;
    float* bsm     = sm + O_BS;
    float* scratch = sm + O_RNH;   // reused after stage B

    const int t = threadIdx.x;
    const int m = blockIdx.x >> 3;
    const int s = blockIdx.x & 7;
    const int w = t >> 5, lane = t & 31;
    const int g = lane >> 2, q = lane & 3;
    const bool evenlane = (lane & 4) == 0;   // g even

    if (t < 32) { asum_sm[t] = 0.f; bsm[t] = bvec[t]; }
    #pragma unroll
    for (int i = 0; i < 4; i++) {
        int idx = i * 256 + t, k = idx >> 5, cp = idx & 31;
        float2 wv = ((const float2*)W)[idx];
        uint32_t H, L; pair2(wv.x, wv.y, H, L);
        WCH[k * WCP + cp] = H; WCL[k * WCP + cp] = L;
    }
    __syncthreads();

    const int kb = w & 1, cbh = (w >> 1) & 1, nsel = w >> 2;
    const int cb0 = 32 * cbh, rb = 16 * w;
    const int npA = evenlane ? ((rb + g) >> 1) : ((rb + g + 7) >> 1);

    float vA[4][4], asl[4][2];
    #pragma unroll
    for (int cb = 0; cb < 4; cb++)
        #pragma unroll
        for (int r = 0; r < 4; r++) vA[cb][r] = 0.f;
    #pragma unroll
    for (int nb = 0; nb < 4; nb++) asl[nb][0] = asl[nb][1] = 0.f;

    const float* Rbase = R + ((size_t)m * Nn + (size_t)s * (Nn / SPLIT)) * Cc;

    for (int tile = 0; tile < TILES; ++tile) {
        if (tile > 0) __syncthreads();   // prior stage B done with Rn/A'
        const float* Rt = Rbase + (size_t)tile * NT * Cc;

        // ---- Stage A + single R read + Rn build
        float dA[4][4];
        #pragma unroll
        for (int nb = 0; nb < 4; nb++) {
            float b0 = bsm[8 * nb + 2 * q], b1 = bsm[8 * nb + 2 * q + 1];
            dA[nb][0] = b0; dA[nb][1] = b1; dA[nb][2] = b0; dA[nb][3] = b1;
        }
        const float2* Rt2 = (const float2*)Rt;
        const int r0 = (rb + g) * 32, r1 = (rb + g + 8) * 32;
        #pragma unroll
        for (int ch = 0; ch < 4; ch++) {
            const int cp = 8 * ch + q;
            float2 v00 = Rt2[r0 + cp],     v10 = Rt2[r1 + cp];
            float2 v01 = Rt2[r0 + cp + 4], v11 = Rt2[r1 + cp + 4];
            // partner-row exchange (g^1): rows (2i,2i+1) pairing
            float p0x = SHF4(v00.x), p0y = SHF4(v00.y);
            float p1x = SHF4(v01.x), p1y = SHF4(v01.y);
            float p2x = SHF4(v10.x), p2y = SHF4(v10.y);
            float p3x = SHF4(v11.x), p3y = SHF4(v11.y);
            const int ci = 16 * ch + 2 * q;
            uint32_t H0, L0, H1, L1;
            if (evenlane) {   // np = (rb+g)/2, lo = own row (even), hi = partner
                pair2(v00.x, p0x, H0, L0); pair2(v00.y, p0y, H1, L1);
                *(uint2*)(RNH + npA * RNP + ci) = make_uint2(H0, H1);
                *(uint2*)(RNL + npA * RNP + ci) = make_uint2(L0, L1);
                pair2(v01.x, p1x, H0, L0); pair2(v01.y, p1y, H1, L1);
                *(uint2*)(RNH + npA * RNP + ci + 8) = make_uint2(H0, H1);
                *(uint2*)(RNL + npA * RNP + ci + 8) = make_uint2(L0, L1);
            } else {          // np for rows (rb+g+7, rb+g+8): lo = partner, hi = own
                pair2(p2x, v10.x, H0, L0); pair2(p2y, v10.y, H1, L1);
                *(uint2*)(RNH + npA * RNP + ci) = make_uint2(H0, H1);
                *(uint2*)(RNL + npA * RNP + ci) = make_uint2(L0, L1);
                pair2(p3x, v11.x, H0, L0); pair2(p3y, v11.y, H1, L1);
                *(uint2*)(RNH + npA * RNP + ci + 8) = make_uint2(H0, H1);
                *(uint2*)(RNL + npA * RNP + ci + 8) = make_uint2(L0, L1);
            }
            // A fragments
            uint32_t Ah0,Al0,Ah1,Al1,Ah2,Al2,Ah3,Al3;
            pair2(v00.x, v00.y, Ah0, Al0);
            pair2(v10.x, v10.y, Ah1, Al1);
            pair2(v01.x, v01.y, Ah2, Al2);
            pair2(v11.x, v11.y, Ah3, Al3);
            #pragma unroll
            for (int nb = 0; nb < 4; nb++) {
                const int kr = (8 * nb + g) * WCP + 8 * ch;
                uint32_t Bh0 = WCH[kr + q], Bh1 = WCH[kr + 4 + q];
                uint32_t Bl0 = WCL[kr + q], Bl1 = WCL[kr + 4 + q];
                MMA_BF16(dA[nb][0],dA[nb][1],dA[nb][2],dA[nb][3], Ah0,Ah1,Ah2,Ah3, Bh0,Bh1);
                MMA_BF16(dA[nb][0],dA[nb][1],dA[nb][2],dA[nb][3], Ah0,Ah1,Ah2,Ah3, Bl0,Bl1);
                MMA_BF16(dA[nb][0],dA[nb][1],dA[nb][2],dA[nb][3], Al0,Al1,Al2,Al3, Bh0,Bh1);
            }
        }

        // ---- softmax over k (rows rb+g, rb+g+8)
        float mx0 = -1e30f, mx1 = -1e30f;
        #pragma unroll
        for (int nb = 0; nb < 4; nb++) {
            mx0 = fmaxf(mx0, fmaxf(dA[nb][0], dA[nb][1]));
            mx1 = fmaxf(mx1, fmaxf(dA[nb][2], dA[nb][3]));
        }
        mx0 = fmaxf(mx0, __shfl_xor_sync(~0u, mx0, 1));
        mx0 = fmaxf(mx0, __shfl_xor_sync(~0u, mx0, 2));
        mx1 = fmaxf(mx1, __shfl_xor_sync(~0u, mx1, 1));
        mx1 = fmaxf(mx1, __shfl_xor_sync(~0u, mx1, 2));
        float s0 = 0.f, s1 = 0.f;
        #pragma unroll
        for (int nb = 0; nb < 4; nb++) {
            dA[nb][0] = __expf(dA[nb][0] - mx0);
            dA[nb][1] = __expf(dA[nb][1] - mx0);
            dA[nb][2] = __expf(dA[nb][2] - mx1);
            dA[nb][3] = __expf(dA[nb][3] - mx1);
            s0 += dA[nb][0] + dA[nb][1];
            s1 += dA[nb][2] + dA[nb][3];
        }
        s0 += __shfl_xor_sync(~0u, s0, 1); s0 += __shfl_xor_sync(~0u, s0, 2);
        s1 += __shfl_xor_sync(~0u, s1, 1); s1 += __shfl_xor_sync(~0u, s1, 2);
        const float inv0 = __fdividef(1.f, s0), inv1 = __fdividef(1.f, s1);
        #pragma unroll
        for (int nb = 0; nb < 4; nb++) {
            #pragma unroll
            for (int j = 0; j < 2; j++) {
                const int k = 8 * nb + 2 * q + j;
                float p0 = dA[nb][j] * inv0, p1 = dA[nb][j + 2] * inv1;
                asl[nb][j] += p0 + p1;
                float o0 = SHF4(p0), o1 = SHF4(p1);
                if (evenlane) {
                    const int np0 = (rb + g) >> 1, np1 = (rb + g + 8) >> 1;
                    uint32_t H, L;
                    pair2(p0, o0, H, L);
                    AKH[k * AKP + np0] = H; AKL[k * AKP + np0] = L;
                    pair2(p1, o1, H, L);
                    AKH[k * AKP + np1] = H; AKL[k * AKP + np1] = L;
                }
            }
        }
        __syncthreads();   // Rn + A' visible

        // ---- Stage B: 16k x 32c over this warp's half of n-chunks
        #pragma unroll
        for (int ci2 = 0; ci2 < 4; ci2++) {
            const int npb = 8 * (4 * nsel + ci2);
            const int a0i = (16 * kb + g) * AKP + npb;
            const int a1i = (16 * kb + g + 8) * AKP + npb;
            uint32_t Ph0 = AKH[a0i + q],     Pl0 = AKL[a0i + q];
            uint32_t Ph1 = AKH[a1i + q],     Pl1 = AKL[a1i + q];
            uint32_t Ph2 = AKH[a0i + 4 + q], Pl2 = AKL[a0i + 4 + q];
            uint32_t Ph3 = AKH[a1i + 4 + q], Pl3 = AKL[a1i + 4 + q];
            #pragma unroll
            for (int cb = 0; cb < 4; cb++) {
                const int c0 = cb0 + 8 * cb;
                const int b0i = (npb + q) * RNP + c0 + g;
                const int b1i = (npb + 4 + q) * RNP + c0 + g;
                uint32_t Rh0 = RNH[b0i], Rl0 = RNL[b0i];
                uint32_t Rh1 = RNH[b1i], Rl1 = RNL[b1i];
                MMA_BF16(vA[cb][0],vA[cb][1],vA[cb][2],vA[cb][3], Ph0,Ph1,Ph2,Ph3, Rh0,Rh1);
                MMA_BF16(vA[cb][0],vA[cb][1],vA[cb][2],vA[cb][3], Ph0,Ph1,Ph2,Ph3, Rl0,Rl1);
                MMA_BF16(vA[cb][0],vA[cb][1],vA[cb][2],vA[cb][3], Pl0,Pl1,Pl2,Pl3, Rh0,Rh1);
            }
        }
    }

    __syncthreads();   // stage B done before scratch reuse
    if (t >= 128) {
        #pragma unroll
        for (int cb = 0; cb < 4; cb++)
            #pragma unroll
            for (int r = 0; r < 4; r++)
                scratch[(4 * cb + r) * 128 + (t - 128)] = vA[cb][r];
    }
    #pragma unroll
    for (int nb = 0; nb < 4; nb++)
        #pragma unroll
        for (int j = 0; j < 2; j++) {
            float v = asl[nb][j];
            v += __shfl_xor_sync(~0u, v, 4);
            v += __shfl_xor_sync(~0u, v, 8);
            v += __shfl_xor_sync(~0u, v, 16);
            if (g == 0) atomicAdd(&asum_sm[8 * nb + 2 * q + j], v);
        }
    __syncthreads();

    if (t < 128) {
        float* outm = out + (size_t)m * Kk * Cc;
        const int k0 = 16 * kb + g, k1 = k0 + 8;
        const float as0 = asum_sm[k0], as1 = asum_sm[k1];
        #pragma unroll
        for (int cb = 0; cb < 4; cb++) {
            const int c = cb0 + 8 * cb + 2 * q;
            float x0 = vA[cb][0] + scratch[(4 * cb + 0) * 128 + t];
            float x1 = vA[cb][1] + scratch[(4 * cb + 1) * 128 + t];
            float x2 = vA[cb][2] + scratch[(4 * cb + 2) * 128 + t];
            float x3 = vA[cb][3] + scratch[(4 * cb + 3) * 128 + t];
            const float2 c0v = *(const float2*)(cent + k0 * 64 + c);
            const float2 c1v = *(const float2*)(cent + k1 * 64 + c);
            atomicAdd(outm + k0 * 64 + c,     x0 - as0 * c0v.x);
            atomicAdd(outm + k0 * 64 + c + 1, x1 - as0 * c0v.y);
            atomicAdd(outm + k1 * 64 + c,     x2 - as1 * c1v.x);
            atomicAdd(outm + k1 * 64 + c + 1, x3 - as1 * c1v.y);
        }
    }
}

extern "C" void kernel_launch(void* const* d_in, const int* in_sizes, int n_in,
                              void* d_out, int out_size) {
    const float* R = (const float*)d_in[0];
    const float* W = (const float*)d_in[1];
    const float* b = (const float*)d_in[2];
    const float* cent = (const float*)d_in[3];
    float* out = (float*)d_out;
    cudaFuncSetAttribute(nv_tc, cudaFuncAttributeMaxDynamicSharedMemorySize, SMEM_BYTES);
    int n4 = out_size / 4;
    nv_zero<<<(n4 + 255) / 256, 256>>>((float4*)out, n4);
    nv_tc<<<256 * SPLIT, 256, SMEM_BYTES>>>(R, W, b, cent, out);
}

// round 12
// speedup vs baseline: 1.0497x; 1.0497x over previous
#include <cuda_runtime.h>
#include <cstdint>

// NetVLAD fused pool, 3-product BF16 mma.sync m16n8k16, sm_103a. Round 12.
// = Round 7 structure (all R via coalesced float4 -> presplit smem; Rc c-packed
// for stage A, Rn n-packed for stage B) + SPLIT=8 (kills 13% wave tail)
// + cvt.rn bf16x2 splits (R9-validated).

#define MMA_BF16(d0,d1,d2,d3, a0,a1,a2,a3, b0,b1) \
  asm volatile("mma.sync.aligned.m16n8k16.row.col.f32.bf16.bf16.f32 " \
      "{%0,%1,%2,%3},{%4,%5,%6,%7},{%8,%9},{%0,%1,%2,%3};" \
      : "+f"(d0),"+f"(d1),"+f"(d2),"+f"(d3) \
      : "r"(a0),"r"(a1),"r"(a2),"r"(a3),"r"(b0),"r"(b1))
#define CVT2(d, lo, hi) \
  asm("cvt.rn.satfinite.bf16x2.f32 %0, %1, %2;" : "=r"(d) : "f"(hi), "f"(lo))

__device__ __forceinline__ float lo16f(uint32_t x){ return __uint_as_float(x << 16); }
__device__ __forceinline__ float hi16f(uint32_t x){ return __uint_as_float(x & 0xFFFF0000u); }
__device__ __forceinline__ void pair2(float x, float y, uint32_t& H, uint32_t& L){
    CVT2(H, x, y);
    CVT2(L, x - lo16f(H), y - hi16f(H));
}

namespace {
constexpr int Nn = 2048, Cc = 64, Kk = 32;
constexpr int SPLIT = 8, NT = 128;
constexpr int TILES = (Nn / SPLIT) / NT;   // 2
constexpr int RCP = 36, RNP = 72, WCP = 36, AKP = 68;
constexpr int O_RCH = 0;
constexpr int O_RCL = O_RCH + NT * RCP;
constexpr int O_RNH = O_RCL + NT * RCP;
constexpr int O_RNL = O_RNH + 64 * RNP;
constexpr int O_WCH = O_RNL + 64 * RNP;
constexpr int O_WCL = O_WCH + Kk * WCP;
constexpr int O_AKH = O_WCL + Kk * WCP;
constexpr int O_AKL = O_AKH + Kk * AKP;
constexpr int O_AS  = O_AKL + Kk * AKP;
constexpr int SMEM_BYTES = (O_AS + 32) * 4;   // ~100.5 KB -> 2 CTAs/SM
}

__global__ void nv_zero(float4* __restrict__ out, int n4) {
    int i = blockIdx.x * blockDim.x + threadIdx.x;
    if (i < n4) out[i] = make_float4(0.f, 0.f, 0.f, 0.f);
}

__global__ __launch_bounds__(256, 2) void nv_tc(
    const float* __restrict__ R, const float* __restrict__ W,
    const float* __restrict__ bvec, const float* __restrict__ cent,
    float* __restrict__ out)
{
    extern __shared__ float sm[];
    uint32_t* RCH = (uint32_t*)(sm + O_RCH);
    uint32_t* RCL = (uint32_t*)(sm + O_RCL);
    uint32_t* RNH = (uint32_t*)(sm + O_RNH);
    uint32_t* RNL = (uint32_t*)(sm + O_RNL);
    uint32_t* WCH = (uint32_t*)(sm + O_WCH);
    uint32_t* WCL = (uint32_t*)(sm + O_WCL);
    uint32_t* AKH = (uint32_t*)(sm + O_AKH);
    uint32_t* AKL = (uint32_t*)(sm + O_AKL);
    float* asum_sm = sm + O_AS;

    const int t = threadIdx.x;
    const int m = blockIdx.x >> 3;
    const int s = blockIdx.x & 7;
    const int w = t >> 5, lane = t & 31;
    const int g = lane >> 2, q = lane & 3;
    const bool evenlane = (lane & 4) == 0;

    if (t < 32) asum_sm[t] = 0.f;
    #pragma unroll
    for (int i = 0; i < 4; i++) {
        int idx = i * 256 + t, k = idx >> 5, cp = idx & 31;
        float2 wv = ((const float2*)W)[idx];
        uint32_t H, L; pair2(wv.x, wv.y, H, L);
        WCH[k * WCP + cp] = H; WCL[k * WCP + cp] = L;
    }

    float bias[4][2];
    #pragma unroll
    for (int nb = 0; nb < 4; nb++) {
        bias[nb][0] = bvec[8 * nb + 2 * q];
        bias[nb][1] = bvec[8 * nb + 2 * q + 1];
    }
    const int kb = w & 1, cb0 = (w >> 1) * 16, rb = 16 * w;
    const int col4 = t & 15, rp0 = t >> 4;

    float vA[2][4], asl[4][2];
    #pragma unroll
    for (int cb = 0; cb < 2; cb++)
        #pragma unroll
        for (int r = 0; r < 4; r++) vA[cb][r] = 0.f;
    #pragma unroll
    for (int nb = 0; nb < 4; nb++) asl[nb][0] = asl[nb][1] = 0.f;

    const float* Rbase = R + ((size_t)m * Nn + (size_t)s * (Nn / SPLIT)) * Cc;

    // prefetch tile 0
    float4 pfa[4], pfb[4];
    {
        const float4* Rg = (const float4*)Rbase;
        #pragma unroll
        for (int j = 0; j < 4; j++) {
            int rp = rp0 + 16 * j;
            pfa[j] = Rg[(2 * rp) * 16 + col4];
            pfb[j] = Rg[(2 * rp + 1) * 16 + col4];
        }
    }

    for (int tile = 0; tile < TILES; ++tile) {
        if (tile > 0) __syncthreads();

        // ---- split + dual-layout store
        #pragma unroll
        for (int j = 0; j < 4; j++) {
            const int rp = rp0 + 16 * j;
            float4 a = pfa[j], b = pfb[j];
            uint2 rc0, rc1, rd0, rd1;
            pair2(a.x, a.y, rc0.x, rd0.x); pair2(a.z, a.w, rc0.y, rd0.y);
            pair2(b.x, b.y, rc1.x, rd1.x); pair2(b.z, b.w, rc1.y, rd1.y);
            *(uint2*)(RCH + (2 * rp) * RCP + 2 * col4)     = make_uint2(rc0.x, rc0.y);
            *(uint2*)(RCL + (2 * rp) * RCP + 2 * col4)     = make_uint2(rd0.x, rd0.y);
            *(uint2*)(RCH + (2 * rp + 1) * RCP + 2 * col4) = make_uint2(rc1.x, rc1.y);
            *(uint2*)(RCL + (2 * rp + 1) * RCP + 2 * col4) = make_uint2(rd1.x, rd1.y);
            uint4 nh, nl;
            pair2(a.x, b.x, nh.x, nl.x);
            pair2(a.y, b.y, nh.y, nl.y);
            pair2(a.z, b.z, nh.z, nl.z);
            pair2(a.w, b.w, nh.w, nl.w);
            *(uint4*)(RNH + rp * RNP + 4 * col4) = nh;
            *(uint4*)(RNL + rp * RNP + 4 * col4) = nl;
        }
        __syncthreads();

        // ---- prefetch next tile
        if (tile + 1 < TILES) {
            const float4* Rg = (const float4*)(Rbase + (size_t)(tile + 1) * NT * Cc);
            #pragma unroll
            for (int j = 0; j < 4; j++) {
                int rp = rp0 + 16 * j;
                pfa[j] = Rg[(2 * rp) * 16 + col4];
                pfb[j] = Rg[(2 * rp + 1) * 16 + col4];
            }
        }

        // ---- Stage A: warp w rows rb..rb+15
        float dA[4][4];
        #pragma unroll
        for (int nb = 0; nb < 4; nb++) {
            dA[nb][0] = bias[nb][0]; dA[nb][1] = bias[nb][1];
            dA[nb][2] = bias[nb][0]; dA[nb][3] = bias[nb][1];
        }
        #pragma unroll
        for (int ch = 0; ch < 4; ch++) {
            const int cpb = 8 * ch;
            const int r0 = (rb + g) * RCP + cpb;
            const int r1 = (rb + g + 8) * RCP + cpb;
            uint32_t Ah0 = RCH[r0 + q],     Al0 = RCL[r0 + q];
            uint32_t Ah1 = RCH[r1 + q],     Al1 = RCL[r1 + q];
            uint32_t Ah2 = RCH[r0 + 4 + q], Al2 = RCL[r0 + 4 + q];
            uint32_t Ah3 = RCH[r1 + 4 + q], Al3 = RCL[r1 + 4 + q];
            #pragma unroll
            for (int nb = 0; nb < 4; nb++) {
                const int kr = (8 * nb + g) * WCP + cpb;
                uint32_t Bh0 = WCH[kr + q], Bh1 = WCH[kr + 4 + q];
                uint32_t Bl0 = WCL[kr + q], Bl1 = WCL[kr + 4 + q];
                MMA_BF16(dA[nb][0],dA[nb][1],dA[nb][2],dA[nb][3], Ah0,Ah1,Ah2,Ah3, Bh0,Bh1);
                MMA_BF16(dA[nb][0],dA[nb][1],dA[nb][2],dA[nb][3], Ah0,Ah1,Ah2,Ah3, Bl0,Bl1);
                MMA_BF16(dA[nb][0],dA[nb][1],dA[nb][2],dA[nb][3], Al0,Al1,Al2,Al3, Bh0,Bh1);
            }
        }

        // ---- softmax over k (rows rb+g, rb+g+8)
        float mx0 = -1e30f, mx1 = -1e30f;
        #pragma unroll
        for (int nb = 0; nb < 4; nb++) {
            mx0 = fmaxf(mx0, fmaxf(dA[nb][0], dA[nb][1]));
            mx1 = fmaxf(mx1, fmaxf(dA[nb][2], dA[nb][3]));
        }
        mx0 = fmaxf(mx0, __shfl_xor_sync(~0u, mx0, 1));
        mx0 = fmaxf(mx0, __shfl_xor_sync(~0u, mx0, 2));
        mx1 = fmaxf(mx1, __shfl_xor_sync(~0u, mx1, 1));
        mx1 = fmaxf(mx1, __shfl_xor_sync(~0u, mx1, 2));
        float s0 = 0.f, s1 = 0.f;
        #pragma unroll
        for (int nb = 0; nb < 4; nb++) {
            dA[nb][0] = __expf(dA[nb][0] - mx0);
            dA[nb][1] = __expf(dA[nb][1] - mx0);
            dA[nb][2] = __expf(dA[nb][2] - mx1);
            dA[nb][3] = __expf(dA[nb][3] - mx1);
            s0 += dA[nb][0] + dA[nb][1];
            s1 += dA[nb][2] + dA[nb][3];
        }
        s0 += __shfl_xor_sync(~0u, s0, 1); s0 += __shfl_xor_sync(~0u, s0, 2);
        s1 += __shfl_xor_sync(~0u, s1, 1); s1 += __shfl_xor_sync(~0u, s1, 2);
        const float inv0 = __fdividef(1.f, s0), inv1 = __fdividef(1.f, s1);
        #pragma unroll
        for (int nb = 0; nb < 4; nb++) {
            #pragma unroll
            for (int j = 0; j < 2; j++) {
                const int k = 8 * nb + 2 * q + j;
                float p0 = dA[nb][j] * inv0, p1 = dA[nb][j + 2] * inv1;
                asl[nb][j] += p0 + p1;
                float o0 = __shfl_xor_sync(~0u, p0, 4);
                float o1 = __shfl_xor_sync(~0u, p1, 4);
                if (evenlane) {
                    const int np0 = (rb + g) >> 1, np1 = (rb + g + 8) >> 1;
                    uint32_t H, L;
                    pair2(p0, o0, H, L);
                    AKH[k * AKP + np0] = H; AKL[k * AKP + np0] = L;
                    pair2(p1, o1, H, L);
                    AKH[k * AKP + np1] = H; AKL[k * AKP + np1] = L;
                }
            }
        }
        __syncthreads();

        // ---- Stage B: V[k][c] += A'[k][n]*R[n][c]
        #pragma unroll 4
        for (int ch = 0; ch < 8; ch++) {
            const int npb = 8 * ch;
            const int a0i = (16 * kb + g) * AKP + npb;
            const int a1i = (16 * kb + g + 8) * AKP + npb;
            uint32_t Ph0 = AKH[a0i + q],     Pl0 = AKL[a0i + q];
            uint32_t Ph1 = AKH[a1i + q],     Pl1 = AKL[a1i + q];
            uint32_t Ph2 = AKH[a0i + 4 + q], Pl2 = AKL[a0i + 4 + q];
            uint32_t Ph3 = AKH[a1i + 4 + q], Pl3 = AKL[a1i + 4 + q];
            #pragma unroll
            for (int cb = 0; cb < 2; cb++) {
                const int c0 = cb0 + 8 * cb;
                const int b0i = (npb + q) * RNP + c0 + g;
                const int b1i = (npb + 4 + q) * RNP + c0 + g;
                uint32_t Rh0 = RNH[b0i], Rl0 = RNL[b0i];
                uint32_t Rh1 = RNH[b1i], Rl1 = RNL[b1i];
                MMA_BF16(vA[cb][0],vA[cb][1],vA[cb][2],vA[cb][3], Ph0,Ph1,Ph2,Ph3, Rh0,Rh1);
                MMA_BF16(vA[cb][0],vA[cb][1],vA[cb][2],vA[cb][3], Ph0,Ph1,Ph2,Ph3, Rl0,Rl1);
                MMA_BF16(vA[cb][0],vA[cb][1],vA[cb][2],vA[cb][3], Pl0,Pl1,Pl2,Pl3, Rh0,Rh1);
            }
        }
    }

    // ---- asum reduce + epilogue
    #pragma unroll
    for (int nb = 0; nb < 4; nb++)
        #pragma unroll
        for (int j = 0; j < 2; j++) {
            float v = asl[nb][j];
            v += __shfl_xor_sync(~0u, v, 4);
            v += __shfl_xor_sync(~0u, v, 8);
            v += __shfl_xor_sync(~0u, v, 16);
            if (g == 0) atomicAdd(&asum_sm[8 * nb + 2 * q + j], v);
        }
    __syncthreads();

    float* outm = out + (size_t)m * Kk * Cc;
    const int k0 = 16 * kb + g, k1 = k0 + 8;
    const float as0 = asum_sm[k0], as1 = asum_sm[k1];
    #pragma unroll
    for (int cb = 0; cb < 2; cb++) {
        const int c = cb0 + 8 * cb + 2 * q;
        const float2 c0v = *(const float2*)(cent + k0 * 64 + c);
        const float2 c1v = *(const float2*)(cent + k1 * 64 + c);
        atomicAdd(outm + k0 * 64 + c,     vA[cb][0] - as0 * c0v.x);
        atomicAdd(outm + k0 * 64 + c + 1, vA[cb][1] - as0 * c0v.y);
        atomicAdd(outm + k1 * 64 + c,     vA[cb][2] - as1 * c1v.x);
        atomicAdd(outm + k1 * 64 + c + 1, vA[cb][3] - as1 * c1v.y);
    }
}

extern "C" void kernel_launch(void* const* d_in, const int* in_sizes, int n_in,
                              void* d_out, int out_size) {
    const float* R = (const float*)d_in[0];
    const float* W = (const float*)d_in[1];
    const float* b = (const float*)d_in[2];
    const float* cent = (const float*)d_in[3];
    float* out = (float*)d_out;
    cudaFuncSetAttribute(nv_tc, cudaFuncAttributeMaxDynamicSharedMemorySize, SMEM_BYTES);
    int n4 = out_size / 4;
    nv_zero<<<(n4 + 255) / 256, 256>>>((float4*)out, n4);
    nv_tc<<<256 * SPLIT, 256, SMEM_BYTES>>>(R, W, b, cent, out);
}

// round 13
// speedup vs baseline: 1.0847x; 1.0333x over previous
#include <cuda_runtime.h>
#include <cstdint>

// NetVLAD fused pool, 3-product BF16 mma.sync m16n8k16, sm_103a. Round 13.
// R7 config (SPLIT=4, grid 1024) + cvt splits + split stage-B accumulators
// (4 chains of 12 instead of 2 of 24) + bias in smem.

#define MMA_BF16(d0,d1,d2,d3, a0,a1,a2,a3, b0,b1) \
  asm volatile("mma.sync.aligned.m16n8k16.row.col.f32.bf16.bf16.f32 " \
      "{%0,%1,%2,%3},{%4,%5,%6,%7},{%8,%9},{%0,%1,%2,%3};" \
      : "+f"(d0),"+f"(d1),"+f"(d2),"+f"(d3) \
      : "r"(a0),"r"(a1),"r"(a2),"r"(a3),"r"(b0),"r"(b1))
#define CVT2(d, lo, hi) \
  asm("cvt.rn.satfinite.bf16x2.f32 %0, %1, %2;" : "=r"(d) : "f"(hi), "f"(lo))

__device__ __forceinline__ float lo16f(uint32_t x){ return __uint_as_float(x << 16); }
__device__ __forceinline__ float hi16f(uint32_t x){ return __uint_as_float(x & 0xFFFF0000u); }
__device__ __forceinline__ void pair2(float x, float y, uint32_t& H, uint32_t& L){
    CVT2(H, x, y);
    CVT2(L, x - lo16f(H), y - hi16f(H));
}

namespace {
constexpr int Nn = 2048, Cc = 64, Kk = 32;
constexpr int SPLIT = 4, NT = 128;
constexpr int TILES = (Nn / SPLIT) / NT;   // 4
constexpr int RCP = 36, RNP = 72, WCP = 36, AKP = 68;
constexpr int O_RCH = 0;
constexpr int O_RCL = O_RCH + NT * RCP;
constexpr int O_RNH = O_RCL + NT * RCP;
constexpr int O_RNL = O_RNH + 64 * RNP;
constexpr int O_WCH = O_RNL + 64 * RNP;
constexpr int O_WCL = O_WCH + Kk * WCP;
constexpr int O_AKH = O_WCL + Kk * WCP;
constexpr int O_AKL = O_AKH + Kk * AKP;
constexpr int O_AS  = O_AKL + Kk * AKP;
constexpr int O_BS  = O_AS + 32;
constexpr int SMEM_BYTES = (O_BS + 32) * 4;   // ~100.6 KB -> 2 CTAs/SM
}

__global__ void nv_zero(float4* __restrict__ out, int n4) {
    int i = blockIdx.x * blockDim.x + threadIdx.x;
    if (i < n4) out[i] = make_float4(0.f, 0.f, 0.f, 0.f);
}

__global__ __launch_bounds__(256, 2) void nv_tc(
    const float* __restrict__ R, const float* __restrict__ W,
    const float* __restrict__ bvec, const float* __restrict__ cent,
    float* __restrict__ out)
{
    extern __shared__ float sm[];
    uint32_t* RCH = (uint32_t*)(sm + O_RCH);
    uint32_t* RCL = (uint32_t*)(sm + O_RCL);
    uint32_t* RNH = (uint32_t*)(sm + O_RNH);
    uint32_t* RNL = (uint32_t*)(sm + O_RNL);
    uint32_t* WCH = (uint32_t*)(sm + O_WCH);
    uint32_t* WCL = (uint32_t*)(sm + O_WCL);
    uint32_t* AKH = (uint32_t*)(sm + O_AKH);
    uint32_t* AKL = (uint32_t*)(sm + O_AKL);
    float* asum_sm = sm + O_AS;
    float* bsm     = sm + O_BS;

    const int t = threadIdx.x;
    const int m = blockIdx.x >> 2;
    const int s = blockIdx.x & 3;
    const int w = t >> 5, lane = t & 31;
    const int g = lane >> 2, q = lane & 3;
    const bool evenlane = (lane & 4) == 0;

    if (t < 32) { asum_sm[t] = 0.f; bsm[t] = bvec[t]; }
    #pragma unroll
    for (int i = 0; i < 4; i++) {
        int idx = i * 256 + t, k = idx >> 5, cp = idx & 31;
        float2 wv = ((const float2*)W)[idx];
        uint32_t H, L; pair2(wv.x, wv.y, H, L);
        WCH[k * WCP + cp] = H; WCL[k * WCP + cp] = L;
    }

    const int kb = w & 1, cb0 = (w >> 1) * 16, rb = 16 * w;
    const int col4 = t & 15, rp0 = t >> 4;

    float vAa[2][4], vAb[2][4], asl[4][2];
    #pragma unroll
    for (int cb = 0; cb < 2; cb++)
        #pragma unroll
        for (int r = 0; r < 4; r++) { vAa[cb][r] = 0.f; vAb[cb][r] = 0.f; }
    #pragma unroll
    for (int nb = 0; nb < 4; nb++) asl[nb][0] = asl[nb][1] = 0.f;

    const float* Rbase = R + ((size_t)m * Nn + (size_t)s * (Nn / SPLIT)) * Cc;

    float4 pfa[4], pfb[4];
    {
        const float4* Rg = (const float4*)Rbase;
        #pragma unroll
        for (int j = 0; j < 4; j++) {
            int rp = rp0 + 16 * j;
            pfa[j] = Rg[(2 * rp) * 16 + col4];
            pfb[j] = Rg[(2 * rp + 1) * 16 + col4];
        }
    }

    for (int tile = 0; tile < TILES; ++tile) {
        if (tile > 0) __syncthreads();

        // split + dual-layout store
        #pragma unroll
        for (int j = 0; j < 4; j++) {
            const int rp = rp0 + 16 * j;
            float4 a = pfa[j], b = pfb[j];
            uint2 rc0, rc1, rd0, rd1;
            pair2(a.x, a.y, rc0.x, rd0.x); pair2(a.z, a.w, rc0.y, rd0.y);
            pair2(b.x, b.y, rc1.x, rd1.x); pair2(b.z, b.w, rc1.y, rd1.y);
            *(uint2*)(RCH + (2 * rp) * RCP + 2 * col4)     = rc0;
            *(uint2*)(RCL + (2 * rp) * RCP + 2 * col4)     = rd0;
            *(uint2*)(RCH + (2 * rp + 1) * RCP + 2 * col4) = rc1;
            *(uint2*)(RCL + (2 * rp + 1) * RCP + 2 * col4) = rd1;
            uint4 nh, nl;
            pair2(a.x, b.x, nh.x, nl.x);
            pair2(a.y, b.y, nh.y, nl.y);
            pair2(a.z, b.z, nh.z, nl.z);
            pair2(a.w, b.w, nh.w, nl.w);
            *(uint4*)(RNH + rp * RNP + 4 * col4) = nh;
            *(uint4*)(RNL + rp * RNP + 4 * col4) = nl;
        }
        __syncthreads();

        if (tile + 1 < TILES) {
            const float4* Rg = (const float4*)(Rbase + (size_t)(tile + 1) * NT * Cc);
            #pragma unroll
            for (int j = 0; j < 4; j++) {
                int rp = rp0 + 16 * j;
                pfa[j] = Rg[(2 * rp) * 16 + col4];
                pfb[j] = Rg[(2 * rp + 1) * 16 + col4];
            }
        }

        // Stage A
        float dA[4][4];
        #pragma unroll
        for (int nb = 0; nb < 4; nb++) {
            float b0 = bsm[8 * nb + 2 * q], b1 = bsm[8 * nb + 2 * q + 1];
            dA[nb][0] = b0; dA[nb][1] = b1; dA[nb][2] = b0; dA[nb][3] = b1;
        }
        #pragma unroll
        for (int ch = 0; ch < 4; ch++) {
            const int cpb = 8 * ch;
            const int r0 = (rb + g) * RCP + cpb;
            const int r1 = (rb + g + 8) * RCP + cpb;
            uint32_t Ah0 = RCH[r0 + q],     Al0 = RCL[r0 + q];
            uint32_t Ah1 = RCH[r1 + q],     Al1 = RCL[r1 + q];
            uint32_t Ah2 = RCH[r0 + 4 + q], Al2 = RCL[r0 + 4 + q];
            uint32_t Ah3 = RCH[r1 + 4 + q], Al3 = RCL[r1 + 4 + q];
            #pragma unroll
            for (int nb = 0; nb < 4; nb++) {
                const int kr = (8 * nb + g) * WCP + cpb;
                uint32_t Bh0 = WCH[kr + q], Bh1 = WCH[kr + 4 + q];
                uint32_t Bl0 = WCL[kr + q], Bl1 = WCL[kr + 4 + q];
                MMA_BF16(dA[nb][0],dA[nb][1],dA[nb][2],dA[nb][3], Ah0,Ah1,Ah2,Ah3, Bh0,Bh1);
                MMA_BF16(dA[nb][0],dA[nb][1],dA[nb][2],dA[nb][3], Ah0,Ah1,Ah2,Ah3, Bl0,Bl1);
                MMA_BF16(dA[nb][0],dA[nb][1],dA[nb][2],dA[nb][3], Al0,Al1,Al2,Al3, Bh0,Bh1);
            }
        }

        // softmax over k
        float mx0 = -1e30f, mx1 = -1e30f;
        #pragma unroll
        for (int nb = 0; nb < 4; nb++) {
            mx0 = fmaxf(mx0, fmaxf(dA[nb][0], dA[nb][1]));
            mx1 = fmaxf(mx1, fmaxf(dA[nb][2], dA[nb][3]));
        }
        mx0 = fmaxf(mx0, __shfl_xor_sync(~0u, mx0, 1));
        mx0 = fmaxf(mx0, __shfl_xor_sync(~0u, mx0, 2));
        mx1 = fmaxf(mx1, __shfl_xor_sync(~0u, mx1, 1));
        mx1 = fmaxf(mx1, __shfl_xor_sync(~0u, mx1, 2));
        float s0 = 0.f, s1 = 0.f;
        #pragma unroll
        for (int nb = 0; nb < 4; nb++) {
            dA[nb][0] = __expf(dA[nb][0] - mx0);
            dA[nb][1] = __expf(dA[nb][1] - mx0);
            dA[nb][2] = __expf(dA[nb][2] - mx1);
            dA[nb][3] = __expf(dA[nb][3] - mx1);
            s0 += dA[nb][0] + dA[nb][1];
            s1 += dA[nb][2] + dA[nb][3];
        }
        s0 += __shfl_xor_sync(~0u, s0, 1); s0 += __shfl_xor_sync(~0u, s0, 2);
        s1 += __shfl_xor_sync(~0u, s1, 1); s1 += __shfl_xor_sync(~0u, s1, 2);
        const float inv0 = __fdividef(1.f, s0), inv1 = __fdividef(1.f, s1);
        #pragma unroll
        for (int nb = 0; nb < 4; nb++) {
            #pragma unroll
            for (int j = 0; j < 2; j++) {
                const int k = 8 * nb + 2 * q + j;
                float p0 = dA[nb][j] * inv0, p1 = dA[nb][j + 2] * inv1;
                asl[nb][j] += p0 + p1;
                float o0 = __shfl_xor_sync(~0u, p0, 4);
                float o1 = __shfl_xor_sync(~0u, p1, 4);
                if (evenlane) {
                    const int np0 = (rb + g) >> 1, np1 = (rb + g + 8) >> 1;
                    uint32_t H, L;
                    pair2(p0, o0, H, L);
                    AKH[k * AKP + np0] = H; AKL[k * AKP + np0] = L;
                    pair2(p1, o1, H, L);
                    AKH[k * AKP + np1] = H; AKL[k * AKP + np1] = L;
                }
            }
        }
        __syncthreads();

        // Stage B: even ch -> vAa, odd ch -> vAb (4 independent MMA chains)
        #pragma unroll 4
        for (int ch = 0; ch < 8; ch++) {
            const int npb = 8 * ch;
            const int a0i = (16 * kb + g) * AKP + npb;
            const int a1i = (16 * kb + g + 8) * AKP + npb;
            uint32_t Ph0 = AKH[a0i + q],     Pl0 = AKL[a0i + q];
            uint32_t Ph1 = AKH[a1i + q],     Pl1 = AKL[a1i + q];
            uint32_t Ph2 = AKH[a0i + 4 + q], Pl2 = AKL[a0i + 4 + q];
            uint32_t Ph3 = AKH[a1i + 4 + q], Pl3 = AKL[a1i + 4 + q];
            float (*vv)[4] = (ch & 1) ? vAb : vAa;
            #pragma unroll
            for (int cb = 0; cb < 2; cb++) {
                const int c0 = cb0 + 8 * cb;
                const int b0i = (npb + q) * RNP + c0 + g;
                const int b1i = (npb + 4 + q) * RNP + c0 + g;
                uint32_t Rh0 = RNH[b0i], Rl0 = RNL[b0i];
                uint32_t Rh1 = RNH[b1i], Rl1 = RNL[b1i];
                MMA_BF16(vv[cb][0],vv[cb][1],vv[cb][2],vv[cb][3], Ph0,Ph1,Ph2,Ph3, Rh0,Rh1);
                MMA_BF16(vv[cb][0],vv[cb][1],vv[cb][2],vv[cb][3], Ph0,Ph1,Ph2,Ph3, Rl0,Rl1);
                MMA_BF16(vv[cb][0],vv[cb][1],vv[cb][2],vv[cb][3], Pl0,Pl1,Pl2,Pl3, Rh0,Rh1);
            }
        }
    }

    // asum reduce + epilogue
    #pragma unroll
    for (int nb = 0; nb < 4; nb++)
        #pragma unroll
        for (int j = 0; j < 2; j++) {
            float v = asl[nb][j];
            v += __shfl_xor_sync(~0u, v, 4);
            v += __shfl_xor_sync(~0u, v, 8);
            v += __shfl_xor_sync(~0u, v, 16);
            if (g == 0) atomicAdd(&asum_sm[8 * nb + 2 * q + j], v);
        }
    __syncthreads();

    float* outm = out + (size_t)m * Kk * Cc;
    const int k0 = 16 * kb + g, k1 = k0 + 8;
    const float as0 = asum_sm[k0], as1 = asum_sm[k1];
    #pragma unroll
    for (int cb = 0; cb < 2; cb++) {
        const int c = cb0 + 8 * cb + 2 * q;
        const float2 c0v = *(const float2*)(cent + k0 * 64 + c);
        const float2 c1v = *(const float2*)(cent + k1 * 64 + c);
        atomicAdd(outm + k0 * 64 + c,     (vAa[cb][0] + vAb[cb][0]) - as0 * c0v.x);
        atomicAdd(outm + k0 * 64 + c + 1, (vAa[cb][1] + vAb[cb][1]) - as0 * c0v.y);
        atomicAdd(outm + k1 * 64 + c,     (vAa[cb][2] + vAb[cb][2]) - as1 * c1v.x);
        atomicAdd(outm + k1 * 64 + c + 1, (vAa[cb][3] + vAb[cb][3]) - as1 * c1v.y);
    }
}

extern "C" void kernel_launch(void* const* d_in, const int* in_sizes, int n_in,
                              void* d_out, int out_size) {
    const float* R = (const float*)d_in[0];
    const float* W = (const float*)d_in[1];
    const float* b = (const float*)d_in[2];
    const float* cent = (const float*)d_in[3];
    float* out = (float*)d_out;
    cudaFuncSetAttribute(nv_tc, cudaFuncAttributeMaxDynamicSharedMemorySize, SMEM_BYTES);
    int n4 = out_size / 4;
    nv_zero<<<(n4 + 255) / 256, 256>>>((float4*)out, n4);
    nv_tc<<<256 * SPLIT, 256, SMEM_BYTES>>>(R, W, b, cent, out);
}

// round 14
// speedup vs baseline: 1.2067x; 1.1125x over previous
#include <cuda_runtime.h>
#include <cstdint>

// NetVLAD fused pool, 3-product BF16 mma.sync m16n8k16, sm_103a. Round 14.
// Rc deleted: stage-A fragments derived from Rn via LDS.64 + PRMT (row-parity
// byte select). Smem 63.7KB -> 3 CTA/SM. No prefetch regs; single vA set.

#define MMA_BF16(d0,d1,d2,d3, a0,a1,a2,a3, b0,b1) \
  asm volatile("mma.sync.aligned.m16n8k16.row.col.f32.bf16.bf16.f32 " \
      "{%0,%1,%2,%3},{%4,%5,%6,%7},{%8,%9},{%0,%1,%2,%3};" \
      : "+f"(d0),"+f"(d1),"+f"(d2),"+f"(d3) \
      : "r"(a0),"r"(a1),"r"(a2),"r"(a3),"r"(b0),"r"(b1))
#define CVT2(d, lo, hi) \
  asm("cvt.rn.satfinite.bf16x2.f32 %0, %1, %2;" : "=r"(d) : "f"(hi), "f"(lo))

__device__ __forceinline__ float lo16f(uint32_t x){ return __uint_as_float(x << 16); }
__device__ __forceinline__ float hi16f(uint32_t x){ return __uint_as_float(x & 0xFFFF0000u); }
__device__ __forceinline__ void pair2(float x, float y, uint32_t& H, uint32_t& L){
    CVT2(H, x, y);
    CVT2(L, x - lo16f(H), y - hi16f(H));
}

namespace {
constexpr int Nn = 2048, Cc = 64, Kk = 32;
constexpr int SPLIT = 4, NT = 128;
constexpr int TILES = (Nn / SPLIT) / NT;   // 4
constexpr int RNP = 72, WCP = 36, AKP = 68;
constexpr int O_RNH = 0;
constexpr int O_RNL = O_RNH + 64 * RNP;        // 4608
constexpr int O_WCH = O_RNL + 64 * RNP;        // 9216
constexpr int O_WCL = O_WCH + Kk * WCP;
constexpr int O_AKH = O_WCL + Kk * WCP;
constexpr int O_AKL = O_AKH + Kk * AKP;
constexpr int O_AS  = O_AKL + Kk * AKP;
constexpr int O_BS  = O_AS + 32;
constexpr int SMEM_BYTES = (O_BS + 32) * 4;    // 63,744 B -> 3 CTA/SM
}

__global__ void nv_zero(float4* __restrict__ out, int n4) {
    int i = blockIdx.x * blockDim.x + threadIdx.x;
    if (i < n4) out[i] = make_float4(0.f, 0.f, 0.f, 0.f);
}

__global__ __launch_bounds__(256, 3) void nv_tc(
    const float* __restrict__ R, const float* __restrict__ W,
    const float* __restrict__ bvec, const float* __restrict__ cent,
    float* __restrict__ out)
{
    extern __shared__ float sm[];
    uint32_t* RNH = (uint32_t*)(sm + O_RNH);
    uint32_t* RNL = (uint32_t*)(sm + O_RNL);
    uint32_t* WCH = (uint32_t*)(sm + O_WCH);
    uint32_t* WCL = (uint32_t*)(sm + O_WCL);
    uint32_t* AKH = (uint32_t*)(sm + O_AKH);
    uint32_t* AKL = (uint32_t*)(sm + O_AKL);
    float* asum_sm = sm + O_AS;
    float* bsm     = sm + O_BS;

    const int t = threadIdx.x;
    const int m = blockIdx.x >> 2;
    const int s = blockIdx.x & 3;
    const int w = t >> 5, lane = t & 31;
    const int g = lane >> 2, q = lane & 3;
    const bool evenlane = (lane & 4) == 0;

    if (t < 32) { asum_sm[t] = 0.f; bsm[t] = bvec[t]; }
    #pragma unroll
    for (int i = 0; i < 4; i++) {
        int idx = i * 256 + t, k = idx >> 5, cp = idx & 31;
        float2 wv = ((const float2*)W)[idx];
        uint32_t H, L; pair2(wv.x, wv.y, H, L);
        WCH[k * WCP + cp] = H; WCL[k * WCP + cp] = L;
    }

    const int kb = w & 1, cb0 = (w >> 1) * 16, rb = 16 * w;
    const int col4 = t & 15, rp0 = t >> 4;
    // stage-A PRMT selector: row rb+g parity = g&1 (rb even)
    const uint32_t psel = (g & 1) ? 0x7632u : 0x5410u;
    const int npg  = (rb + g) >> 1;
    const int npg8 = (rb + g + 8) >> 1;

    float vA[2][4], asl[4][2];
    #pragma unroll
    for (int cb = 0; cb < 2; cb++)
        #pragma unroll
        for (int r = 0; r < 4; r++) vA[cb][r] = 0.f;
    #pragma unroll
    for (int nb = 0; nb < 4; nb++) asl[nb][0] = asl[nb][1] = 0.f;

    const float* Rbase = R + ((size_t)m * Nn + (size_t)s * (Nn / SPLIT)) * Cc;

    for (int tile = 0; tile < TILES; ++tile) {
        if (tile > 0) __syncthreads();   // prior stage B done with Rn/AK
        const float4* Rg = (const float4*)(Rbase + (size_t)tile * NT * Cc);

        // ---- load + split + store Rn (n-pair packed) only
        #pragma unroll
        for (int j = 0; j < 4; j++) {
            const int rp = rp0 + 16 * j;
            float4 a = Rg[(2 * rp) * 16 + col4];
            float4 b = Rg[(2 * rp + 1) * 16 + col4];
            uint4 nh, nl;
            pair2(a.x, b.x, nh.x, nl.x);
            pair2(a.y, b.y, nh.y, nl.y);
            pair2(a.z, b.z, nh.z, nl.z);
            pair2(a.w, b.w, nh.w, nl.w);
            *(uint4*)(RNH + rp * RNP + 4 * col4) = nh;
            *(uint4*)(RNL + rp * RNP + 4 * col4) = nl;
        }
        __syncthreads();

        // ---- Stage A: fragments from Rn via uint2 LDS + PRMT
        float dA[4][4];
        #pragma unroll
        for (int nb = 0; nb < 4; nb++) {
            float b0 = bsm[8 * nb + 2 * q], b1 = bsm[8 * nb + 2 * q + 1];
            dA[nb][0] = b0; dA[nb][1] = b1; dA[nb][2] = b0; dA[nb][3] = b1;
        }
        #pragma unroll
        for (int ch = 0; ch < 4; ch++) {
            const int ci = 16 * ch + 2 * q;
            uint2 h0 = *(uint2*)(RNH + npg  * RNP + ci);
            uint2 l0 = *(uint2*)(RNL + npg  * RNP + ci);
            uint2 h1 = *(uint2*)(RNH + npg8 * RNP + ci);
            uint2 l1 = *(uint2*)(RNL + npg8 * RNP + ci);
            uint2 h2 = *(uint2*)(RNH + npg  * RNP + ci + 8);
            uint2 l2 = *(uint2*)(RNL + npg  * RNP + ci + 8);
            uint2 h3 = *(uint2*)(RNH + npg8 * RNP + ci + 8);
            uint2 l3 = *(uint2*)(RNL + npg8 * RNP + ci + 8);
            uint32_t Ah0 = __byte_perm(h0.x, h0.y, psel), Al0 = __byte_perm(l0.x, l0.y, psel);
            uint32_t Ah1 = __byte_perm(h1.x, h1.y, psel), Al1 = __byte_perm(l1.x, l1.y, psel);
            uint32_t Ah2 = __byte_perm(h2.x, h2.y, psel), Al2 = __byte_perm(l2.x, l2.y, psel);
            uint32_t Ah3 = __byte_perm(h3.x, h3.y, psel), Al3 = __byte_perm(l3.x, l3.y, psel);
            #pragma unroll
            for (int nb = 0; nb < 4; nb++) {
                const int kr = (8 * nb + g) * WCP + 8 * ch;
                uint32_t Bh0 = WCH[kr + q], Bh1 = WCH[kr + 4 + q];
                uint32_t Bl0 = WCL[kr + q], Bl1 = WCL[kr + 4 + q];
                MMA_BF16(dA[nb][0],dA[nb][1],dA[nb][2],dA[nb][3], Ah0,Ah1,Ah2,Ah3, Bh0,Bh1);
                MMA_BF16(dA[nb][0],dA[nb][1],dA[nb][2],dA[nb][3], Ah0,Ah1,Ah2,Ah3, Bl0,Bl1);
                MMA_BF16(dA[nb][0],dA[nb][1],dA[nb][2],dA[nb][3], Al0,Al1,Al2,Al3, Bh0,Bh1);
            }
        }

        // ---- softmax over k (rows rb+g, rb+g+8)
        float mx0 = -1e30f, mx1 = -1e30f;
        #pragma unroll
        for (int nb = 0; nb < 4; nb++) {
            mx0 = fmaxf(mx0, fmaxf(dA[nb][0], dA[nb][1]));
            mx1 = fmaxf(mx1, fmaxf(dA[nb][2], dA[nb][3]));
        }
        mx0 = fmaxf(mx0, __shfl_xor_sync(~0u, mx0, 1));
        mx0 = fmaxf(mx0, __shfl_xor_sync(~0u, mx0, 2));
        mx1 = fmaxf(mx1, __shfl_xor_sync(~0u, mx1, 1));
        mx1 = fmaxf(mx1, __shfl_xor_sync(~0u, mx1, 2));
        float s0 = 0.f, s1 = 0.f;
        #pragma unroll
        for (int nb = 0; nb < 4; nb++) {
            dA[nb][0] = __expf(dA[nb][0] - mx0);
            dA[nb][1] = __expf(dA[nb][1] - mx0);
            dA[nb][2] = __expf(dA[nb][2] - mx1);
            dA[nb][3] = __expf(dA[nb][3] - mx1);
            s0 += dA[nb][0] + dA[nb][1];
            s1 += dA[nb][2] + dA[nb][3];
        }
        s0 += __shfl_xor_sync(~0u, s0, 1); s0 += __shfl_xor_sync(~0u, s0, 2);
        s1 += __shfl_xor_sync(~0u, s1, 1); s1 += __shfl_xor_sync(~0u, s1, 2);
        const float inv0 = __fdividef(1.f, s0), inv1 = __fdividef(1.f, s1);
        #pragma unroll
        for (int nb = 0; nb < 4; nb++) {
            #pragma unroll
            for (int j = 0; j < 2; j++) {
                const int k = 8 * nb + 2 * q + j;
                float p0 = dA[nb][j] * inv0, p1 = dA[nb][j + 2] * inv1;
                asl[nb][j] += p0 + p1;
                float o0 = __shfl_xor_sync(~0u, p0, 4);
                float o1 = __shfl_xor_sync(~0u, p1, 4);
                if (evenlane) {
                    const int np0 = (rb + g) >> 1, np1 = (rb + g + 8) >> 1;
                    uint32_t H, L;
                    pair2(p0, o0, H, L);
                    AKH[k * AKP + np0] = H; AKL[k * AKP + np0] = L;
                    pair2(p1, o1, H, L);
                    AKH[k * AKP + np1] = H; AKL[k * AKP + np1] = L;
                }
            }
        }
        __syncthreads();   // A' visible

        // ---- Stage B: V[k][c] += A'[k][n]*R[n][c]
        #pragma unroll 4
        for (int ch = 0; ch < 8; ch++) {
            const int npb = 8 * ch;
            const int a0i = (16 * kb + g) * AKP + npb;
            const int a1i = (16 * kb + g + 8) * AKP + npb;
            uint32_t Ph0 = AKH[a0i + q],     Pl0 = AKL[a0i + q];
            uint32_t Ph1 = AKH[a1i + q],     Pl1 = AKL[a1i + q];
            uint32_t Ph2 = AKH[a0i + 4 + q], Pl2 = AKL[a0i + 4 + q];
            uint32_t Ph3 = AKH[a1i + 4 + q], Pl3 = AKL[a1i + 4 + q];
            #pragma unroll
            for (int cb = 0; cb < 2; cb++) {
                const int c0 = cb0 + 8 * cb;
                const int b0i = (npb + q) * RNP + c0 + g;
                const int b1i = (npb + 4 + q) * RNP + c0 + g;
                uint32_t Rh0 = RNH[b0i], Rl0 = RNL[b0i];
                uint32_t Rh1 = RNH[b1i], Rl1 = RNL[b1i];
                MMA_BF16(vA[cb][0],vA[cb][1],vA[cb][2],vA[cb][3], Ph0,Ph1,Ph2,Ph3, Rh0,Rh1);
                MMA_BF16(vA[cb][0],vA[cb][1],vA[cb][2],vA[cb][3], Ph0,Ph1,Ph2,Ph3, Rl0,Rl1);
                MMA_BF16(vA[cb][0],vA[cb][1],vA[cb][2],vA[cb][3], Pl0,Pl1,Pl2,Pl3, Rh0,Rh1);
            }
        }
    }

    // ---- asum reduce + epilogue
    #pragma unroll
    for (int nb = 0; nb < 4; nb++)
        #pragma unroll
        for (int j = 0; j < 2; j++) {
            float v = asl[nb][j];
            v += __shfl_xor_sync(~0u, v, 4);
            v += __shfl_xor_sync(~0u, v, 8);
            v += __shfl_xor_sync(~0u, v, 16);
            if (g == 0) atomicAdd(&asum_sm[8 * nb + 2 * q + j], v);
        }
    __syncthreads();

    float* outm = out + (size_t)m * Kk * Cc;
    const int k0 = 16 * kb + g, k1 = k0 + 8;
    const float as0 = asum_sm[k0], as1 = asum_sm[k1];
    #pragma unroll
    for (int cb = 0; cb < 2; cb++) {
        const int c = cb0 + 8 * cb + 2 * q;
        const float2 c0v = *(const float2*)(cent + k0 * 64 + c);
        const float2 c1v = *(const float2*)(cent + k1 * 64 + c);
        atomicAdd(outm + k0 * 64 + c,     vA[cb][0] - as0 * c0v.x);
        atomicAdd(outm + k0 * 64 + c + 1, vA[cb][1] - as0 * c0v.y);
        atomicAdd(outm + k1 * 64 + c,     vA[cb][2] - as1 * c1v.x);
        atomicAdd(outm + k1 * 64 + c + 1, vA[cb][3] - as1 * c1v.y);
    }
}

extern "C" void kernel_launch(void* const* d_in, const int* in_sizes, int n_in,
                              void* d_out, int out_size) {
    const float* R = (const float*)d_in[0];
    const float* W = (const float*)d_in[1];
    const float* b = (const float*)d_in[2];
    const float* cent = (const float*)d_in[3];
    float* out = (float*)d_out;
    cudaFuncSetAttribute(nv_tc, cudaFuncAttributeMaxDynamicSharedMemorySize, SMEM_BYTES);
    int n4 = out_size / 4;
    nv_zero<<<(n4 + 255) / 256, 256>>>((float4*)out, n4);
    nv_tc<<<256 * SPLIT, 256, SMEM_BYTES>>>(R, W, b, cent, out);
}